// round 15
// baseline (speedup 1.0000x reference)
#include <cuda_runtime.h>
#include <cuda_fp16.h>

#define EPSF 1e-6f
#define FULLM 0xffffffffu

constexpr int cV = 128, cK = 32, cC = 256;
constexpr int cL = 4, cN = 4096, cF = 16;
constexpr int cE = 8192, cB = 512;
constexpr int cB4 = cB / 4;            // 128 float4 groups per fp32 row
constexpr int cBu4 = cB / 8;           // 64 uint4 (16B) groups per half row
constexpr int NT   = 512;
constexpr int BPSM = 2;
constexpr int GRID = 256;              // NWARP = 4096 = cN -> 1 row-task per warp
constexpr int NWARP = GRID * NT / 32;
constexpr float LN2F = 0.69314718055994530942f;

// ---- scratch (static __device__ per allocation rules) ----
__device__ __align__(16) __half d_lwlin[cV * cK * cC]; // 2 MB linear mantissas (rowmax=1)
__device__ __align__(16) float  d_eIn[cV * cK];        // input row scales (log2)
__device__ __align__(16) int4   d_fw[cL * cN * cF];    // 4 MB {c0*cBu4, c1*cBu4, W, 0}
__device__ __align__(16) float  d_R[cN];               // linear root weights
__device__ __align__(16) float  d_eA[cN];              // scale ping
__device__ __align__(16) float  d_eB[cN];              // scale pong
__device__ __align__(16) int    d_xT[cV * cB];         // transposed inputs
__device__ __align__(16) __half d_nmA[cN * cB];        // 4 MB mantissas ping
__device__ __align__(16) __half d_nmB[cN * cB];        // 4 MB mantissas pong
__device__ __align__(16) float  d_fin[cN * cB];        // 8 MB final log2 values

// ---- grid barrier state ----
__device__ unsigned d_bar_count = 0;
__device__ volatile unsigned d_bar_gen = 0;

// ---- single-instruction MUFU ops ----
__device__ __forceinline__ float ex2(float x) {
    float y; asm("ex2.approx.ftz.f32 %0, %1;" : "=f"(y) : "f"(x)); return y;
}
__device__ __forceinline__ float lg2(float x) {
    float y; asm("lg2.approx.ftz.f32 %0, %1;" : "=f"(y) : "f"(x)); return y;
}
__device__ __forceinline__ float rcp(float x) {
    float y; asm("rcp.approx.ftz.f32 %0, %1;" : "=f"(y) : "f"(x)); return y;
}
__device__ __forceinline__ __half2 u2h2(unsigned u) {
    __half2 h; *reinterpret_cast<unsigned*>(&h) = u; return h;
}
__device__ __forceinline__ unsigned h2u(__half2 h) {
    return *reinterpret_cast<unsigned*>(&h);
}

// ==================================================================
// grid barrier (all GRID blocks resident).
// ==================================================================
__device__ __forceinline__ void grid_barrier() {
    __syncthreads();
    if (threadIdx.x == 0) {
        __threadfence();
        unsigned gen = d_bar_gen;
        unsigned t   = atomicAdd(&d_bar_count, 1u);
        if (t == GRID - 1) {
            d_bar_count = 0;
            __threadfence();
            d_bar_gen = gen + 1;
        } else {
            while (d_bar_gen == gen) { __nanosleep(64); }
        }
        __threadfence();
    }
    __syncthreads();
}

// ==================================================================
// SINGLE PERSISTENT kernel:
//  P: prep (input-norm, fused tables, root-norm, transpose)
//  0: SMEM-staged input gather -> d_nmA
//  4x fused linear layers (fp16 mantissas, per-row log2 scales)
//  root LSE
// ==================================================================
__global__ void __launch_bounds__(NT, BPSM) k_persist(const float* __restrict__ ip,
                                                      const float* __restrict__ sp,
                                                      const float* __restrict__ rp,
                                                      const int*   __restrict__ inputs,
                                                      const int*   __restrict__ sci,
                                                      const int*   __restrict__ pc,
                                                      float* __restrict__ out) {
    __shared__ __align__(16) char s_raw[2 * NT * 16];   // 16 KB, multi-purpose
    float4* s_m = reinterpret_cast<float4*>(s_raw);
    float4* s_s = s_m + NT;
    const int t    = threadIdx.x;
    const int lane = t & 31;
    const int wid  = (blockIdx.x * NT + t) >> 5;   // global warp id, 0..4095

    // ---------- phase P: prep ----------
    {
        // (a) input-param rows: exactly one warp per (v,k) row (4096 warps)
        {
            const float* row = ip + wid * cC;
            float v[8];
            float tot = 0.f, mx = 0.f;
#pragma unroll
            for (int i = 0; i < 8; i++) {
                v[i] = row[lane + i * 32] + EPSF;
                tot += v[i];
                mx = fmaxf(mx, v[i]);
            }
#pragma unroll
            for (int o = 16; o; o >>= 1) {
                tot += __shfl_xor_sync(FULLM, tot, o);
                mx = fmaxf(mx, __shfl_xor_sync(FULLM, mx, o));
            }
            float inv = 1.f / mx;
#pragma unroll
            for (int i = 0; i < 8; i++)
                d_lwlin[wid * cC + lane + i * 32] = __float2half_rn(v[i] * inv);
            if (lane == 0) d_eIn[wid] = lg2(mx / tot);   // true = mant * 2^e
        }
        int gid = blockIdx.x * NT + t;
        // (b) fused tables: one thread per (l,n)
        if (gid < cL * cN) {
            int l = gid / cN;
            const float* spr  = sp  + gid * cF;
            const int*   scir = sci + gid * cF;
            const int2*  pcl  = reinterpret_cast<const int2*>(pc) + l * cE;
            float w[cF];
            float tot = 0.f;
#pragma unroll
            for (int f = 0; f < cF; f++) { w[f] = spr[f] + EPSF; tot += w[f]; }
            float inv = 1.f / tot;
            int4* dst = d_fw + gid * cF;
#pragma unroll
            for (int f = 0; f < cF; f++) {
                int2 c = pcl[scir[f]];
                dst[f] = make_int4(c.x * cBu4, c.y * cBu4, __float_as_int(w[f] * inv), 0);
            }
        }
        // (c) transpose inputs (B,V) -> xT (V,B)
        if (gid < cV * cB) {
            int bb = gid >> 7;
            int vv = gid & 127;
            d_xT[vv * cB + bb] = inputs[gid];
        }
        // (d) root norm: block 0 (512 threads, 8 elems each)
        if (blockIdx.x == 0) {
            float* red = reinterpret_cast<float*>(s_raw);
            float v[8];
            float s = 0.f;
#pragma unroll
            for (int i = 0; i < 8; i++) {
                v[i] = rp[t + i * 512] + EPSF;
                s += v[i];
            }
            red[t] = s;
            __syncthreads();
            for (int o = 256; o; o >>= 1) {
                if (t < o) red[t] += red[t + o];
                __syncthreads();
            }
            float inv = 1.f / red[0];
#pragma unroll
            for (int i = 0; i < 8; i++) d_R[t + i * 512] = v[i] * inv;
            __syncthreads();
        }
    }
    grid_barrier();

    // ---------- phase 0: SMEM-staged input gather -> d_nmA ----------
    {
        __half* s_lw = reinterpret_cast<__half*>(s_raw);   // 16 rows x 256 = 8 KB
        int v  = blockIdx.x >> 1;                 // 0..127
        int ks = (blockIdx.x & 1) << 4;           // 0 or 16
        reinterpret_cast<float4*>(s_lw)[t] =
            reinterpret_cast<const float4*>(d_lwlin + (v * cK + ks) * cC)[t];
        __syncthreads();
        int x = d_xT[v * cB + t];                 // thread t <-> batch b = t
#pragma unroll
        for (int k = 0; k < 16; k++)
            d_nmA[(v * cK + ks + k) * cB + t] = s_lw[k * cC + x];
        __syncthreads();
    }
    grid_barrier();

    // ---------- 4 fused linear layers: warp = full row n = wid ----------
    __half* nm_src = d_nmA;
    __half* nm_dst = d_nmB;
    const float* esrc = d_eIn;
    const int n = wid;
    for (int l = 0; l < cL; l++) {
        float* edst = (l & 1) ? d_eB : d_eA;
        const int4*  fwl = d_fw + l * cN * cF;
        const uint4* nmS = reinterpret_cast<const uint4*>(nm_src);

        // lane f (mirrored at f+16) owns table entry f
        int4 pm = __ldg(fwl + n * cF + (lane & 15));
        // per-row scale: row = pm.x / cBu4 = pm.x >> 6
        float g_my = __ldg(esrc + (pm.x >> 6)) + __ldg(esrc + (pm.y >> 6));
        float G = g_my;
#pragma unroll
        for (int o = 1; o < 16; o <<= 1)
            G = fmaxf(G, __shfl_xor_sync(FULLM, G, o));
        float coef_my = __int_as_float(pm.z) * ex2(g_my - G);

        // depth-2 pipelined gathers: 4 uint4 per f, 8 in flight
        int sx = __shfl_sync(FULLM, pm.x, 0);
        int sy = __shfl_sync(FULLM, pm.y, 0);
        uint4 a0A = nmS[sx + lane], a1A = nmS[sx + 32 + lane];
        uint4 b0A = nmS[sy + lane], b1A = nmS[sy + 32 + lane];
        sx = __shfl_sync(FULLM, pm.x, 1);
        sy = __shfl_sync(FULLM, pm.y, 1);
        uint4 a0B = nmS[sx + lane], a1B = nmS[sx + 32 + lane];
        uint4 b0B = nmS[sy + lane], b1B = nmS[sy + 32 + lane];

        float acc[16];
#pragma unroll
        for (int j = 0; j < 16; j++) acc[j] = 0.f;

#pragma unroll
        for (int f = 0; f < cF; f++) {
            float cf = __shfl_sync(FULLM, coef_my, f);
            uint4 a0 = a0A, a1 = a1A, b0 = b0A, b1 = b1A;
            a0A = a0B; a1A = a1B; b0A = b0B; b1A = b1B;
            if (f + 2 < cF) {
                sx = __shfl_sync(FULLM, pm.x, f + 2);
                sy = __shfl_sync(FULLM, pm.y, f + 2);
                a0B = nmS[sx + lane]; a1B = nmS[sx + 32 + lane];
                b0B = nmS[sy + lane]; b1B = nmS[sy + 32 + lane];
            }
            float2 p;
            p = __half22float2(__hmul2(u2h2(a0.x), u2h2(b0.x))); acc[0] += cf * p.x; acc[1] += cf * p.y;
            p = __half22float2(__hmul2(u2h2(a0.y), u2h2(b0.y))); acc[2] += cf * p.x; acc[3] += cf * p.y;
            p = __half22float2(__hmul2(u2h2(a0.z), u2h2(b0.z))); acc[4] += cf * p.x; acc[5] += cf * p.y;
            p = __half22float2(__hmul2(u2h2(a0.w), u2h2(b0.w))); acc[6] += cf * p.x; acc[7] += cf * p.y;
            p = __half22float2(__hmul2(u2h2(a1.x), u2h2(b1.x))); acc[8]  += cf * p.x; acc[9]  += cf * p.y;
            p = __half22float2(__hmul2(u2h2(a1.y), u2h2(b1.y))); acc[10] += cf * p.x; acc[11] += cf * p.y;
            p = __half22float2(__hmul2(u2h2(a1.z), u2h2(b1.z))); acc[12] += cf * p.x; acc[13] += cf * p.y;
            p = __half22float2(__hmul2(u2h2(a1.w), u2h2(b1.w))); acc[14] += cf * p.x; acc[15] += cf * p.y;
        }

        if (l < cL - 1) {
            // row renormalize: rowmax -> 1, fold into e_out
            float qm = acc[0];
#pragma unroll
            for (int j = 1; j < 16; j++) qm = fmaxf(qm, acc[j]);
#pragma unroll
            for (int o = 16; o; o >>= 1)
                qm = fmaxf(qm, __shfl_xor_sync(FULLM, qm, o));
            float ri = rcp(qm);
            uint4 o4;
            o4.x = h2u(__floats2half2_rn(acc[0] * ri, acc[1] * ri));
            o4.y = h2u(__floats2half2_rn(acc[2] * ri, acc[3] * ri));
            o4.z = h2u(__floats2half2_rn(acc[4] * ri, acc[5] * ri));
            o4.w = h2u(__floats2half2_rn(acc[6] * ri, acc[7] * ri));
            __stcg(reinterpret_cast<uint4*>(nm_dst) + n * cBu4 + lane, o4);
            o4.x = h2u(__floats2half2_rn(acc[8]  * ri, acc[9]  * ri));
            o4.y = h2u(__floats2half2_rn(acc[10] * ri, acc[11] * ri));
            o4.z = h2u(__floats2half2_rn(acc[12] * ri, acc[13] * ri));
            o4.w = h2u(__floats2half2_rn(acc[14] * ri, acc[15] * ri));
            __stcg(reinterpret_cast<uint4*>(nm_dst) + n * cBu4 + 32 + lane, o4);
            if (lane == 0) edst[n] = G + lg2(qm);
        } else {
            // final layer: emit fp32 log2 values for the root reduction
            float4* fd = reinterpret_cast<float4*>(d_fin) + n * cB4;
            float4 w;
            w.x = G + lg2(acc[0]); w.y = G + lg2(acc[1]);
            w.z = G + lg2(acc[2]); w.w = G + lg2(acc[3]);
            __stcg(fd + lane * 2, w);
            w.x = G + lg2(acc[4]); w.y = G + lg2(acc[5]);
            w.z = G + lg2(acc[6]); w.w = G + lg2(acc[7]);
            __stcg(fd + lane * 2 + 1, w);
            w.x = G + lg2(acc[8]);  w.y = G + lg2(acc[9]);
            w.z = G + lg2(acc[10]); w.w = G + lg2(acc[11]);
            __stcg(fd + 64 + lane * 2, w);
            w.x = G + lg2(acc[12]); w.y = G + lg2(acc[13]);
            w.z = G + lg2(acc[14]); w.w = G + lg2(acc[15]);
            __stcg(fd + 64 + lane * 2 + 1, w);
        }
        grid_barrier();

        __half* tmp = nm_src; nm_src = nm_dst; nm_dst = tmp;
        esrc = edst;
    }

    // ---------- root: out[b] = ln2 * (m + lg2(sum_n R_n 2^(x_nb - m))) ----------
    if (blockIdx.x < cB4) {
        const int g = blockIdx.x;              // float4 batch group
        const float4* nmp = reinterpret_cast<const float4*>(d_fin);

        float R0 = __ldg(d_R + t);
        float4 m = nmp[t * cB4 + g];
        float4 s = make_float4(R0, R0, R0, R0);
#pragma unroll
        for (int k = 1; k < cN / NT; k++) {
            int   nn = t + k * NT;
            float R = __ldg(d_R + nn);
            float4 x = nmp[nn * cB4 + g];
            s.x += R * ex2(x.x - m.x);
            s.y += R * ex2(x.y - m.y);
            s.z += R * ex2(x.z - m.z);
            s.w += R * ex2(x.w - m.w);
        }
        s_m[t] = m; s_s[t] = s;
        __syncthreads();
        for (int o = NT / 2; o; o >>= 1) {
            if (t < o) {
                float4 m1 = s_m[t], m2 = s_m[t + o];
                float4 s1 = s_s[t], s2 = s_s[t + o];
                float4 mm, ss;
                mm.x = fmaxf(m1.x, m2.x);
                mm.y = fmaxf(m1.y, m2.y);
                mm.z = fmaxf(m1.z, m2.z);
                mm.w = fmaxf(m1.w, m2.w);
                ss.x = s1.x * ex2(m1.x - mm.x) + s2.x * ex2(m2.x - mm.x);
                ss.y = s1.y * ex2(m1.y - mm.y) + s2.y * ex2(m2.y - mm.y);
                ss.z = s1.z * ex2(m1.z - mm.z) + s2.z * ex2(m2.z - mm.z);
                ss.w = s1.w * ex2(m1.w - mm.w) + s2.w * ex2(m2.w - mm.w);
                s_m[t] = mm; s_s[t] = ss;
            }
            __syncthreads();
        }
        if (t == 0) {
            float4 m0 = s_m[0], s0 = s_s[0];
            out[g * 4 + 0] = (m0.x + lg2(s0.x)) * LN2F;
            out[g * 4 + 1] = (m0.y + lg2(s0.y)) * LN2F;
            out[g * 4 + 2] = (m0.z + lg2(s0.z)) * LN2F;
            out[g * 4 + 3] = (m0.w + lg2(s0.w)) * LN2F;
        }
    }
}

// ==================================================================
extern "C" void kernel_launch(void* const* d_in, const int* in_sizes, int n_in,
                              void* d_out, int out_size) {
    const int*   inputs = (const int*)d_in[0];    // (B, V)
    const int*   pc     = (const int*)d_in[1];    // (L, E, 2)
    const int*   sci    = (const int*)d_in[2];    // (L, N, F)
    const float* ip     = (const float*)d_in[3];  // (V, K, C)
    const float* sp     = (const float*)d_in[4];  // (L, N, F)
    const float* rp     = (const float*)d_in[5];  // (N,)
    float* out = (float*)d_out;                   // (B,)

    k_persist<<<GRID, NT>>>(ip, sp, rp, inputs, sci, pc, out);
}